// round 1
// baseline (speedup 1.0000x reference)
#include <cuda_runtime.h>
#include <cuda_bf16.h>
#include <math.h>

// Problem constants
#define S_LEN 2048
#define E_DIM 4096
#define H_NUM 32
#define D_DIM 128
#define BS_BLK 64
#define NB_BLK 32
#define GATE_DIM 64

// -------------------- device scratch (no allocations allowed) --------------------
__device__ float g_Q[S_LEN * E_DIM];
__device__ float g_K[S_LEN * E_DIM];
__device__ float g_V[S_LEN * E_DIM];
__device__ float g_C[S_LEN * E_DIM];
__device__ float g_bmax[H_NUM * NB_BLK * NB_BLK];
__device__ float g_qb[H_NUM * NB_BLK * D_DIM];
__device__ float g_kb[H_NUM * NB_BLK * D_DIM];
__device__ float g_gq[H_NUM * NB_BLK * GATE_DIM];
__device__ float g_gk[H_NUM * NB_BLK * GATE_DIM];

// -------------------- SGEMM: C[m][n] = sum_k A[m][k] * B[n][k] --------------------
// 128x128 tile, BK=8, 256 threads, 8x8 microtile. M,N,K divisible by 128/8.
__global__ __launch_bounds__(256) void sgemm_nt(const float* __restrict__ A,
                                                const float* __restrict__ B,
                                                float* __restrict__ C,
                                                int M, int N, int K) {
    __shared__ float As[8][128];
    __shared__ float Bs[8][128];
    const int bm = blockIdx.y * 128;
    const int bn = blockIdx.x * 128;
    const int tid = threadIdx.x;
    const int lr = tid >> 1;          // 0..127
    const int lc = (tid & 1) * 4;     // 0 or 4
    const int tx = tid & 15;
    const int ty = tid >> 4;

    float acc[8][8];
#pragma unroll
    for (int i = 0; i < 8; i++)
#pragma unroll
        for (int j = 0; j < 8; j++) acc[i][j] = 0.f;

    const float* Ap = A + (size_t)(bm + lr) * K + lc;
    const float* Bp = B + (size_t)(bn + lr) * K + lc;

    for (int k0 = 0; k0 < K; k0 += 8) {
        float4 av = *(const float4*)(Ap + k0);
        float4 bv = *(const float4*)(Bp + k0);
        As[lc + 0][lr] = av.x; As[lc + 1][lr] = av.y;
        As[lc + 2][lr] = av.z; As[lc + 3][lr] = av.w;
        Bs[lc + 0][lr] = bv.x; Bs[lc + 1][lr] = bv.y;
        Bs[lc + 2][lr] = bv.z; Bs[lc + 3][lr] = bv.w;
        __syncthreads();
#pragma unroll
        for (int kk = 0; kk < 8; kk++) {
            float ar[8], br[8];
            *(float4*)(ar)     = *(const float4*)&As[kk][ty * 8];
            *(float4*)(ar + 4) = *(const float4*)&As[kk][ty * 8 + 4];
            *(float4*)(br)     = *(const float4*)&Bs[kk][tx * 8];
            *(float4*)(br + 4) = *(const float4*)&Bs[kk][tx * 8 + 4];
#pragma unroll
            for (int i = 0; i < 8; i++)
#pragma unroll
                for (int j = 0; j < 8; j++) acc[i][j] += ar[i] * br[j];
        }
        __syncthreads();
    }

#pragma unroll
    for (int i = 0; i < 8; i++) {
        float* cp = C + (size_t)(bm + ty * 8 + i) * N + bn + tx * 8;
        *(float4*)(cp)     = make_float4(acc[i][0], acc[i][1], acc[i][2], acc[i][3]);
        *(float4*)(cp + 4) = make_float4(acc[i][4], acc[i][5], acc[i][6], acc[i][7]);
    }
}

// -------------------- RoPE (in-place on g_Q and g_K) --------------------
// pair (d, d+64) within each head: out[d] = x1*c1 - x2*s1 ; out[d+64] = x2*c2 + x1*s2
__global__ __launch_bounds__(256) void rope_kernel(const float* __restrict__ cs,
                                                   const float* __restrict__ sn) {
    const int PAIRS = S_LEN * H_NUM * (D_DIM / 2);  // 4194304
    int idx = blockIdx.x * blockDim.x + threadIdx.x;
    if (idx >= 2 * PAIRS) return;
    float* X = (idx >= PAIRS) ? g_K : g_Q;
    int p = (idx >= PAIRS) ? idx - PAIRS : idx;
    int s = p / (H_NUM * 64);
    int r = p % (H_NUM * 64);
    int h = r / 64;
    int d = r % 64;
    size_t base = (size_t)s * E_DIM + h * D_DIM + d;
    float x1 = X[base];
    float x2 = X[base + 64];
    float c1 = cs[s * D_DIM + d],      s1 = sn[s * D_DIM + d];
    float c2 = cs[s * D_DIM + d + 64], s2 = sn[s * D_DIM + d + 64];
    X[base]      = x1 * c1 - x2 * s1;
    X[base + 64] = x2 * c2 + x1 * s2;
}

// -------------------- Flash attention + block_max --------------------
// grid (32 q-tiles, 32 heads), 128 threads: 2 threads per row (64-dim halves).
// smem: KV tile 64x128 (K then V, reused), SC score tile 64x65 (padded).
__global__ __launch_bounds__(128) void flash_kernel() {
    extern __shared__ float smem[];
    float* KV = smem;              // 64*128
    float* SC = smem + 64 * 128;   // 64*65 (col 64 spare; rows 0..3 spare used for warp maxes)

    const int qt = blockIdx.x;
    const int h  = blockIdx.y;
    const int tid = threadIdx.x;
    const int row = tid >> 1;
    const int half = tid & 1;
    const int lane = tid & 31;
    const int warp = tid >> 5;
    const int qi = qt * 64 + row;
    const float scale = 0.08838834764831845f;  // 1/sqrt(128)

    float qreg[64];
    {
        const float* qp = g_Q + (size_t)qi * E_DIM + h * D_DIM + half * 64;
#pragma unroll
        for (int i = 0; i < 16; i++) ((float4*)qreg)[i] = ((const float4*)qp)[i];
    }
    float acc[64];
#pragma unroll
    for (int i = 0; i < 64; i++) acc[i] = 0.f;
    float m = -INFINITY, l = 0.f;

    for (int kt = 0; kt <= qt; ++kt) {
        __syncthreads();  // previous V-phase reads done
        // load K tile
        {
            const float* kp = g_K + (size_t)(kt * 64) * E_DIM + h * D_DIM;
#pragma unroll
            for (int i = 0; i < 16; i++) {
                int c4 = tid + i * 128;
                int r = c4 >> 5, c = c4 & 31;
                ((float4*)KV)[r * 32 + c] = ((const float4*)(kp + (size_t)r * E_DIM))[c];
            }
        }
        __syncthreads();

        float tmax = -INFINITY;
        for (int j = 0; j < 64; j++) {
            float partial = 0.f;
            const float* kr = KV + j * 128 + half * 64;
#pragma unroll
            for (int d4 = 0; d4 < 16; d4++) {
                float4 k4 = ((const float4*)kr)[d4];
                partial += qreg[d4 * 4 + 0] * k4.x + qreg[d4 * 4 + 1] * k4.y +
                           qreg[d4 * 4 + 2] * k4.z + qreg[d4 * 4 + 3] * k4.w;
            }
            // convergent shuffle (mask applied AFTER)
            float s = (partial + __shfl_xor_sync(0xffffffffu, partial, 1)) * scale;
            bool valid = (kt * 64 + j) <= qi;
            s = valid ? s : -INFINITY;
            if (half == 0) SC[row * 65 + j] = s;
            tmax = fmaxf(tmax, s);
        }
        // block max -> g_bmax
        float wm = tmax;
#pragma unroll
        for (int o = 16; o; o >>= 1) wm = fmaxf(wm, __shfl_xor_sync(0xffffffffu, wm, o));
        if (lane == 0) SC[warp * 65 + 64] = wm;
        __syncthreads();  // scores + warp maxes visible; K reads done
        if (tid == 0) {
            float bm = fmaxf(fmaxf(SC[64], SC[65 + 64]),
                             fmaxf(SC[2 * 65 + 64], SC[3 * 65 + 64]));
            g_bmax[(h * NB_BLK + qt) * NB_BLK + kt] = bm;
        }
        // load V tile (overwrites K; concurrent with tid0's SC reads above — disjoint)
        {
            const float* vp = g_V + (size_t)(kt * 64) * E_DIM + h * D_DIM;
#pragma unroll
            for (int i = 0; i < 16; i++) {
                int c4 = tid + i * 128;
                int r = c4 >> 5, c = c4 & 31;
                ((float4*)KV)[r * 32 + c] = ((const float4*)(vp + (size_t)r * E_DIM))[c];
            }
        }
        __syncthreads();

        // online softmax update
        float mnew = fmaxf(m, tmax);
        float corr = __expf(m - mnew);
        l *= corr;
#pragma unroll
        for (int d = 0; d < 64; d++) acc[d] *= corr;
        const int jmax = (kt == qt) ? (row + 1) : 64;
        float lsum = 0.f;
        for (int j = 0; j < jmax; j++) {
            float p = __expf(SC[row * 65 + j] - mnew);
            lsum += p;
            const float* vr = KV + j * 128 + half * 64;
#pragma unroll
            for (int d4 = 0; d4 < 16; d4++) {
                float4 v4 = ((const float4*)vr)[d4];
                acc[d4 * 4 + 0] += p * v4.x;
                acc[d4 * 4 + 1] += p * v4.y;
                acc[d4 * 4 + 2] += p * v4.z;
                acc[d4 * 4 + 3] += p * v4.w;
            }
        }
        l += lsum;
        m = mnew;
    }

    float inv = 1.f / l;
    float* cp = g_C + (size_t)qi * E_DIM + h * D_DIM + half * 64;
#pragma unroll
    for (int d4 = 0; d4 < 16; d4++) {
        float4 o4 = make_float4(acc[d4 * 4 + 0] * inv, acc[d4 * 4 + 1] * inv,
                                acc[d4 * 4 + 2] * inv, acc[d4 * 4 + 3] * inv);
        ((float4*)cp)[d4] = o4;
    }
}

// -------------------- block means of rotated Q,K --------------------
__global__ __launch_bounds__(128) void block_mean_kernel() {
    const int nb = blockIdx.x, h = blockIdx.y, d = threadIdx.x;
    float sq = 0.f, sk = 0.f;
    for (int r = 0; r < 64; r++) {
        size_t idx = (size_t)(nb * 64 + r) * E_DIM + h * D_DIM + d;
        sq += g_Q[idx];
        sk += g_K[idx];
    }
    g_qb[(h * NB_BLK + nb) * D_DIM + d] = sq * (1.f / 64.f);
    g_kb[(h * NB_BLK + nb) * D_DIM + d] = sk * (1.f / 64.f);
}

// -------------------- gate projections gq/gk --------------------
__global__ __launch_bounds__(128) void gate_proj_kernel(const float* __restrict__ Wgq,
                                                        const float* __restrict__ Wgk) {
    const int nb = blockIdx.x, h = blockIdx.y, t = threadIdx.x;
    const int g = t & 63;
    const bool isK = t >= 64;
    const float* src = isK ? g_kb : g_qb;
    const float* W = isK ? Wgk : Wgq;
    float a = 0.f;
    const float* sp = src + (h * NB_BLK + nb) * D_DIM;
    const float* wp = W + g * D_DIM;
#pragma unroll
    for (int d = 0; d < D_DIM; d++) a += sp[d] * wp[d];
    (isK ? g_gk : g_gq)[(h * NB_BLK + nb) * GATE_DIM + g] = a;
}

// -------------------- per-head 1024-wide softmax helpers --------------------
__device__ __forceinline__ float block_reduce_max(float v, float* red, int t) {
#pragma unroll
    for (int o = 16; o; o >>= 1) v = fmaxf(v, __shfl_xor_sync(0xffffffffu, v, o));
    if ((t & 31) == 0) red[t >> 5] = v;
    __syncthreads();
    if (t < 32) {
        float x = red[t];
#pragma unroll
        for (int o = 16; o; o >>= 1) x = fmaxf(x, __shfl_xor_sync(0xffffffffu, x, o));
        if (t == 0) red[0] = x;
    }
    __syncthreads();
    float r = red[0];
    __syncthreads();
    return r;
}
__device__ __forceinline__ float block_reduce_sum(float v, float* red, int t) {
#pragma unroll
    for (int o = 16; o; o >>= 1) v += __shfl_xor_sync(0xffffffffu, v, o);
    if ((t & 31) == 0) red[t >> 5] = v;
    __syncthreads();
    if (t < 32) {
        float x = red[t];
#pragma unroll
        for (int o = 16; o; o >>= 1) x += __shfl_xor_sync(0xffffffffu, x, o);
        if (t == 0) red[0] = x;
    }
    __syncthreads();
    float r = red[0];
    __syncthreads();
    return r;
}

__global__ __launch_bounds__(1024) void gate_pred_kernel(float* __restrict__ out) {
    __shared__ float red[32];
    const int h = blockIdx.x, t = threadIdx.x;
    const int qn = t >> 5, kn = t & 31;
    float logit = -INFINITY;
    if (kn <= qn) {
        const float* a = g_gq + (h * NB_BLK + qn) * GATE_DIM;
        const float* b = g_gk + (h * NB_BLK + kn) * GATE_DIM;
        float acc = 0.f;
#pragma unroll
        for (int g = 0; g < GATE_DIM; g++) acc += a[g] * b[g];
        logit = acc * 0.125f;  // 1/sqrt(64)
    }
    float M = block_reduce_max(logit, red, t);
    float e = (logit == -INFINITY) ? 0.f : expf(logit - M);
    float L = block_reduce_sum(e, red, t);
    out[h * 1024 + t] = e / L;
}

__global__ __launch_bounds__(1024) void gate_target_kernel(float* __restrict__ out) {
    __shared__ float red[32];
    const int h = blockIdx.x, t = threadIdx.x;
    const int qn = t >> 5, kn = t & 31;
    float logit = -INFINITY;
    if (kn <= qn) {
        float b = g_bmax[h * 1024 + t];
        b = fminf(fmaxf(b, -50.f), 50.f);
        logit = b * 0.5f;  // / GATE_TEMP (=2)
    }
    float M = block_reduce_max(logit, red, t);
    float e = (logit == -INFINITY) ? 0.f : expf(logit - M);
    float L = block_reduce_sum(e, red, t);
    out[h * 1024 + t] = e / L;
}

// -------------------- launch --------------------
extern "C" void kernel_launch(void* const* d_in, const int* in_sizes, int n_in,
                              void* d_out, int out_size) {
    const float* hs   = (const float*)d_in[0];
    const float* cosp = (const float*)d_in[1];
    const float* sinp = (const float*)d_in[2];
    const float* Wq   = (const float*)d_in[3];
    const float* Wk   = (const float*)d_in[4];
    const float* Wv   = (const float*)d_in[5];
    const float* Wo   = (const float*)d_in[6];
    const float* Wgq  = (const float*)d_in[7];
    const float* Wgk  = (const float*)d_in[8];
    float* out = (float*)d_out;

    void *pQ, *pK, *pV, *pC;
    cudaGetSymbolAddress(&pQ, g_Q);
    cudaGetSymbolAddress(&pK, g_K);
    cudaGetSymbolAddress(&pV, g_V);
    cudaGetSymbolAddress(&pC, g_C);

    const int FLASH_SMEM = (64 * 128 + 64 * 65) * 4;  // 49408
    cudaFuncSetAttribute(flash_kernel, cudaFuncAttributeMaxDynamicSharedMemorySize, FLASH_SMEM);

    dim3 gg(E_DIM / 128, S_LEN / 128);
    sgemm_nt<<<gg, 256>>>(hs, Wq, (float*)pQ, S_LEN, E_DIM, E_DIM);
    sgemm_nt<<<gg, 256>>>(hs, Wk, (float*)pK, S_LEN, E_DIM, E_DIM);
    sgemm_nt<<<gg, 256>>>(hs, Wv, (float*)pV, S_LEN, E_DIM, E_DIM);

    rope_kernel<<<(2 * S_LEN * H_NUM * 64 + 255) / 256, 256>>>(cosp, sinp);

    flash_kernel<<<dim3(NB_BLK, H_NUM), 128, FLASH_SMEM>>>();

    block_mean_kernel<<<dim3(NB_BLK, H_NUM), 128>>>();
    gate_proj_kernel<<<dim3(NB_BLK, H_NUM), 128>>>(Wgq, Wgk);

    gate_pred_kernel<<<H_NUM, 1024>>>(out + (size_t)S_LEN * E_DIM);
    gate_target_kernel<<<H_NUM, 1024>>>(out + (size_t)S_LEN * E_DIM + H_NUM * NB_BLK * NB_BLK);

    sgemm_nt<<<gg, 256>>>((const float*)pC, Wo, out, S_LEN, E_DIM, E_DIM);
}

// round 5
// speedup vs baseline: 1.9757x; 1.9757x over previous
#include <cuda_runtime.h>
#include <cuda_bf16.h>
#include <math.h>
#include <cstdint>

// Problem constants
#define S_LEN 2048
#define E_DIM 4096
#define H_NUM 32
#define D_DIM 128
#define BS_BLK 64
#define NB_BLK 32
#define GATE_DIM 64

// GEMM tiling
#define BM 128
#define BN 128
#define BK 32

// Single dynamic-smem declaration shared by all kernels.
extern __shared__ char dynsmem[];

// -------------------- device scratch (no allocations allowed) --------------------
__device__ float g_Q[S_LEN * E_DIM];
__device__ float g_K[S_LEN * E_DIM];
__device__ float g_V[S_LEN * E_DIM];
__device__ float g_C[S_LEN * E_DIM];
__device__ float g_bmax[H_NUM * NB_BLK * NB_BLK];
__device__ float g_qb[H_NUM * NB_BLK * D_DIM];
__device__ float g_kb[H_NUM * NB_BLK * D_DIM];
__device__ float g_gq[H_NUM * NB_BLK * GATE_DIM];
__device__ float g_gk[H_NUM * NB_BLK * GATE_DIM];
// split-bf16 scratch
__device__ __nv_bfloat16 g_Ah[S_LEN * E_DIM];
__device__ __nv_bfloat16 g_Al[S_LEN * E_DIM];
__device__ __nv_bfloat16 g_Wh[4][E_DIM * E_DIM];
__device__ __nv_bfloat16 g_Wl[4][E_DIM * E_DIM];

// -------------------- helpers --------------------
__device__ __forceinline__ uint32_t smem_u32(const void* p) {
    uint32_t a;
    asm("{ .reg .u64 t; cvta.to.shared.u64 t, %1; cvt.u32.u64 %0, t; }" : "=r"(a) : "l"(p));
    return a;
}
__device__ __forceinline__ void cp16(uint32_t dst, const void* src) {
    asm volatile("cp.async.cg.shared.global [%0], [%1], 16;" :: "r"(dst), "l"(src));
}
__device__ __forceinline__ void ldsm4(uint32_t* r, uint32_t addr) {
    asm volatile("ldmatrix.sync.aligned.m8n8.x4.shared.b16 {%0,%1,%2,%3}, [%4];"
                 : "=r"(r[0]), "=r"(r[1]), "=r"(r[2]), "=r"(r[3]) : "r"(addr));
}
__device__ __forceinline__ void mma16816(float* d, const uint32_t* a, const uint32_t* b) {
    asm volatile(
        "mma.sync.aligned.m16n8k16.row.col.f32.bf16.bf16.f32 "
        "{%0,%1,%2,%3}, {%4,%5,%6,%7}, {%8,%9}, {%0,%1,%2,%3};"
        : "+f"(d[0]), "+f"(d[1]), "+f"(d[2]), "+f"(d[3])
        : "r"(a[0]), "r"(a[1]), "r"(a[2]), "r"(a[3]), "r"(b[0]), "r"(b[1]));
}

// Swizzled byte offset inside a 128x32-bf16 tile (rows of 64B; 2-row 128B
// super-rows, chunk XOR by superrow) -> conflict-free ldmatrix.
__device__ __forceinline__ uint32_t sw_off(int r, int c4) {
    return (uint32_t)(((r >> 1) << 7) + (((((r & 1) << 2) + c4) ^ ((r >> 1) & 7)) << 4));
}

// -------------------- split fp32 -> (hi, lo) bf16 --------------------
__global__ __launch_bounds__(256) void split_kernel(const float* __restrict__ src,
                                                    __nv_bfloat16* __restrict__ hi,
                                                    __nv_bfloat16* __restrict__ lo, int n4) {
    int i = blockIdx.x * blockDim.x + threadIdx.x;
    if (i >= n4) return;
    float4 x = ((const float4*)src)[i];
    float xs[4] = {x.x, x.y, x.z, x.w};
    uint32_t hp[2], lp[2];
#pragma unroll
    for (int j = 0; j < 2; j++) {
        __nv_bfloat16 h0 = __float2bfloat16(xs[2 * j]);
        __nv_bfloat16 h1 = __float2bfloat16(xs[2 * j + 1]);
        __nv_bfloat16 l0 = __float2bfloat16(xs[2 * j] - __bfloat162float(h0));
        __nv_bfloat16 l1 = __float2bfloat16(xs[2 * j + 1] - __bfloat162float(h1));
        hp[j] = ((uint32_t)__bfloat16_as_ushort(h1) << 16) | __bfloat16_as_ushort(h0);
        lp[j] = ((uint32_t)__bfloat16_as_ushort(l1) << 16) | __bfloat16_as_ushort(l0);
    }
    ((uint2*)hi)[i] = make_uint2(hp[0], hp[1]);
    ((uint2*)lo)[i] = make_uint2(lp[0], lp[1]);
}

// -------------------- mma.sync split-bf16 GEMM: C[m][n] = sum_k A[m][k]*B[n][k] -----
// 128x128 tile, BK=32, 512 threads (4x4 warps, 32x32 warp tile), double-buffered.
// smem per stage: Ah(8K) Al(8K) Bh(8K) Bl(8K) = 32KB; 2 stages.
#define GSTG 32768
#define GEMM_SMEM (2 * GSTG)

__device__ __forceinline__ void load_tile_mma(uint32_t dstbase, const __nv_bfloat16* src,
                                              int row0, int K, int k0, int tid) {
    // 128 rows x 32 cols bf16 = 512 chunks of 16B; 512 threads -> 1 chunk each
    int r = tid >> 2, c4 = tid & 3;
    cp16(dstbase + sw_off(r, c4), src + (size_t)(row0 + r) * K + k0 + c4 * 8);
}

__global__ __launch_bounds__(512, 1) void gemm_tc(const __nv_bfloat16* __restrict__ Ah,
                                                  const __nv_bfloat16* __restrict__ Al,
                                                  const __nv_bfloat16* __restrict__ Bh,
                                                  const __nv_bfloat16* __restrict__ Bl,
                                                  float* __restrict__ C, int K, int Ncols) {
    uint32_t sb = smem_u32(dynsmem);
    const int tid = threadIdx.x;
    const int wid = tid >> 5, lane = tid & 31;
    const int warp_m = wid >> 2, warp_n = wid & 3;  // 4x4 warp grid
    const int base_m = warp_m * 32, base_n = warp_n * 32;
    const int bm = blockIdx.y * BM, bn = blockIdx.x * BN;

    float acc[2][4][4];
#pragma unroll
    for (int i = 0; i < 2; i++)
#pragma unroll
        for (int j = 0; j < 4; j++)
#pragma unroll
            for (int q = 0; q < 4; q++) acc[i][j][q] = 0.f;

    const int NKI = K / BK;

    // prologue: stage 0
    load_tile_mma(sb + 0,     Ah, bm, K, 0, tid);
    load_tile_mma(sb + 8192,  Al, bm, K, 0, tid);
    load_tile_mma(sb + 16384, Bh, bn, K, 0, tid);
    load_tile_mma(sb + 24576, Bl, bn, K, 0, tid);
    asm volatile("cp.async.commit_group;");

    // precomputed ldmatrix lane offsets
    const int a_r = base_m + (lane & 15);          // + tm*16
    const int a_cs = lane >> 4;                    // + ks*2
    const int b_n = base_n + (lane & 7) + ((lane >> 4) & 1) * 8;  // + tj*16
    const int b_cs = (lane >> 3) & 1;              // + ks*2

    for (int it = 0; it < NKI; ++it) {
        int cur = it & 1;
        if (it + 1 < NKI) {
            uint32_t sn = sb + (cur ^ 1) * GSTG;
            int k0 = (it + 1) * BK;
            load_tile_mma(sn + 0,     Ah, bm, K, k0, tid);
            load_tile_mma(sn + 8192,  Al, bm, K, k0, tid);
            load_tile_mma(sn + 16384, Bh, bn, K, k0, tid);
            load_tile_mma(sn + 24576, Bl, bn, K, k0, tid);
            asm volatile("cp.async.commit_group;");
            asm volatile("cp.async.wait_group 1;");
        } else {
            asm volatile("cp.async.wait_group 0;");
        }
        __syncthreads();

        uint32_t sA_h = sb + cur * GSTG;
        uint32_t sA_l = sA_h + 8192;
        uint32_t sB_h = sA_h + 16384;
        uint32_t sB_l = sA_h + 24576;

#pragma unroll
        for (int ks = 0; ks < 2; ++ks) {
            uint32_t ah[2][4], al[2][4], bh[2][4], bl[2][4];
#pragma unroll
            for (int tm = 0; tm < 2; tm++) {
                uint32_t off = sw_off(a_r + tm * 16, ks * 2 + a_cs);
                ldsm4(ah[tm], sA_h + off);
                ldsm4(al[tm], sA_l + off);
            }
#pragma unroll
            for (int tj = 0; tj < 2; tj++) {
                uint32_t off = sw_off(b_n + tj * 16, ks * 2 + b_cs);
                ldsm4(bh[tj], sB_h + off);
                ldsm4(bl[tj], sB_l + off);
            }
#pragma unroll
            for (int tm = 0; tm < 2; tm++)
#pragma unroll
                for (int tn = 0; tn < 4; tn++) {
                    const uint32_t* pbh = &bh[tn >> 1][(tn & 1) * 2];
                    const uint32_t* pbl = &bl[tn >> 1][(tn & 1) * 2];
                    mma16816(acc[tm][tn], ah[tm], pbh);
                    mma16816(acc[tm][tn], ah[tm], pbl);
                    mma16816(acc[tm][tn], al[tm], pbh);
                }
        }
        __syncthreads();
    }

    // epilogue
#pragma unroll
    for (int tm = 0; tm < 2; tm++)
#pragma unroll
        for (int tn = 0; tn < 4; tn++) {
            int row = bm + base_m + tm * 16 + (lane >> 2);
            int col = bn + base_n + tn * 8 + 2 * (lane & 3);
            float* p0 = C + (size_t)row * Ncols + col;
            float* p1 = C + (size_t)(row + 8) * Ncols + col;
            p0[0] = acc[tm][tn][0];
            p0[1] = acc[tm][tn][1];
            p1[0] = acc[tm][tn][2];
            p1[1] = acc[tm][tn][3];
        }
}

// -------------------- RoPE (in-place on g_Q and g_K) --------------------
__global__ __launch_bounds__(256) void rope_kernel(const float* __restrict__ cs,
                                                   const float* __restrict__ sn) {
    const int PAIRS = S_LEN * H_NUM * (D_DIM / 2);
    int idx = blockIdx.x * blockDim.x + threadIdx.x;
    if (idx >= 2 * PAIRS) return;
    float* X = (idx >= PAIRS) ? g_K : g_Q;
    int p = (idx >= PAIRS) ? idx - PAIRS : idx;
    int s = p / (H_NUM * 64);
    int r = p % (H_NUM * 64);
    int h = r / 64;
    int d = r % 64;
    size_t base = (size_t)s * E_DIM + h * D_DIM + d;
    float x1 = X[base];
    float x2 = X[base + 64];
    float c1 = cs[s * D_DIM + d], s1 = sn[s * D_DIM + d];
    float c2 = cs[s * D_DIM + d + 64], s2 = sn[s * D_DIM + d + 64];
    X[base] = x1 * c1 - x2 * s1;
    X[base + 64] = x2 * c2 + x1 * s2;
}

// -------------------- Flash attention + block_max (fp32) --------------------
__global__ __launch_bounds__(128) void flash_kernel() {
    float* smem = (float*)dynsmem;
    float* KV = smem;
    float* SC = smem + 64 * 128;

    const int qt = blockIdx.x;
    const int h = blockIdx.y;
    const int tid = threadIdx.x;
    const int row = tid >> 1;
    const int half = tid & 1;
    const int lane = tid & 31;
    const int warp = tid >> 5;
    const int qi = qt * 64 + row;
    const float scale = 0.08838834764831845f;

    float qreg[64];
    {
        const float* qp = g_Q + (size_t)qi * E_DIM + h * D_DIM + half * 64;
#pragma unroll
        for (int i = 0; i < 16; i++) ((float4*)qreg)[i] = ((const float4*)qp)[i];
    }
    float acc[64];
#pragma unroll
    for (int i = 0; i < 64; i++) acc[i] = 0.f;
    float m = -INFINITY, l = 0.f;

    for (int kt = 0; kt <= qt; ++kt) {
        __syncthreads();
        {
            const float* kp = g_K + (size_t)(kt * 64) * E_DIM + h * D_DIM;
#pragma unroll
            for (int i = 0; i < 16; i++) {
                int c4 = tid + i * 128;
                int r = c4 >> 5, c = c4 & 31;
                ((float4*)KV)[r * 32 + c] = ((const float4*)(kp + (size_t)r * E_DIM))[c];
            }
        }
        __syncthreads();

        float tmax = -INFINITY;
        for (int j = 0; j < 64; j++) {
            float partial = 0.f;
            const float* kr = KV + j * 128 + half * 64;
#pragma unroll
            for (int d4 = 0; d4 < 16; d4++) {
                float4 k4 = ((const float4*)kr)[d4];
                partial += qreg[d4 * 4 + 0] * k4.x + qreg[d4 * 4 + 1] * k4.y +
                           qreg[d4 * 4 + 2] * k4.z + qreg[d4 * 4 + 3] * k4.w;
            }
            float s = (partial + __shfl_xor_sync(0xffffffffu, partial, 1)) * scale;
            bool valid = (kt * 64 + j) <= qi;
            s = valid ? s : -INFINITY;
            if (half == 0) SC[row * 65 + j] = s;
            tmax = fmaxf(tmax, s);
        }
        float wm = tmax;
#pragma unroll
        for (int o = 16; o; o >>= 1) wm = fmaxf(wm, __shfl_xor_sync(0xffffffffu, wm, o));
        if (lane == 0) SC[warp * 65 + 64] = wm;
        __syncthreads();
        if (tid == 0) {
            float bm = fmaxf(fmaxf(SC[64], SC[65 + 64]),
                             fmaxf(SC[2 * 65 + 64], SC[3 * 65 + 64]));
            g_bmax[(h * NB_BLK + qt) * NB_BLK + kt] = bm;
        }
        {
            const float* vp = g_V + (size_t)(kt * 64) * E_DIM + h * D_DIM;
#pragma unroll
            for (int i = 0; i < 16; i++) {
                int c4 = tid + i * 128;
                int r = c4 >> 5, c = c4 & 31;
                ((float4*)KV)[r * 32 + c] = ((const float4*)(vp + (size_t)r * E_DIM))[c];
            }
        }
        __syncthreads();

        float mnew = fmaxf(m, tmax);
        float corr = __expf(m - mnew);
        l *= corr;
#pragma unroll
        for (int d = 0; d < 64; d++) acc[d] *= corr;
        const int jmax = (kt == qt) ? (row + 1) : 64;
        float lsum = 0.f;
        for (int j = 0; j < jmax; j++) {
            float p = __expf(SC[row * 65 + j] - mnew);
            lsum += p;
            const float* vr = KV + j * 128 + half * 64;
#pragma unroll
            for (int d4 = 0; d4 < 16; d4++) {
                float4 v4 = ((const float4*)vr)[d4];
                acc[d4 * 4 + 0] += p * v4.x;
                acc[d4 * 4 + 1] += p * v4.y;
                acc[d4 * 4 + 2] += p * v4.z;
                acc[d4 * 4 + 3] += p * v4.w;
            }
        }
        l += lsum;
        m = mnew;
    }

    float inv = 1.f / l;
    float* cp = g_C + (size_t)qi * E_DIM + h * D_DIM + half * 64;
#pragma unroll
    for (int d4 = 0; d4 < 16; d4++) {
        ((float4*)cp)[d4] = make_float4(acc[d4 * 4 + 0] * inv, acc[d4 * 4 + 1] * inv,
                                        acc[d4 * 4 + 2] * inv, acc[d4 * 4 + 3] * inv);
    }
}

// -------------------- block means --------------------
__global__ __launch_bounds__(128) void block_mean_kernel() {
    const int nb = blockIdx.x, h = blockIdx.y, d = threadIdx.x;
    float sq = 0.f, sk = 0.f;
    for (int r = 0; r < 64; r++) {
        size_t idx = (size_t)(nb * 64 + r) * E_DIM + h * D_DIM + d;
        sq += g_Q[idx];
        sk += g_K[idx];
    }
    g_qb[(h * NB_BLK + nb) * D_DIM + d] = sq * (1.f / 64.f);
    g_kb[(h * NB_BLK + nb) * D_DIM + d] = sk * (1.f / 64.f);
}

// -------------------- gate projections --------------------
__global__ __launch_bounds__(128) void gate_proj_kernel(const float* __restrict__ Wgq,
                                                        const float* __restrict__ Wgk) {
    const int nb = blockIdx.x, h = blockIdx.y, t = threadIdx.x;
    const int g = t & 63;
    const bool isK = t >= 64;
    const float* src = isK ? g_kb : g_qb;
    const float* W = isK ? Wgk : Wgq;
    float a = 0.f;
    const float* sp = src + (h * NB_BLK + nb) * D_DIM;
    const float* wp = W + g * D_DIM;
#pragma unroll
    for (int d = 0; d < D_DIM; d++) a += sp[d] * wp[d];
    (isK ? g_gk : g_gq)[(h * NB_BLK + nb) * GATE_DIM + g] = a;
}

// -------------------- softmax helpers --------------------
__device__ __forceinline__ float block_reduce_max(float v, float* red, int t) {
#pragma unroll
    for (int o = 16; o; o >>= 1) v = fmaxf(v, __shfl_xor_sync(0xffffffffu, v, o));
    if ((t & 31) == 0) red[t >> 5] = v;
    __syncthreads();
    if (t < 32) {
        float x = red[t];
#pragma unroll
        for (int o = 16; o; o >>= 1) x = fmaxf(x, __shfl_xor_sync(0xffffffffu, x, o));
        if (t == 0) red[0] = x;
    }
    __syncthreads();
    float r = red[0];
    __syncthreads();
    return r;
}
__device__ __forceinline__ float block_reduce_sum(float v, float* red, int t) {
#pragma unroll
    for (int o = 16; o; o >>= 1) v += __shfl_xor_sync(0xffffffffu, v, o);
    if ((t & 31) == 0) red[t >> 5] = v;
    __syncthreads();
    if (t < 32) {
        float x = red[t];
#pragma unroll
        for (int o = 16; o; o >>= 1) x += __shfl_xor_sync(0xffffffffu, x, o);
        if (t == 0) red[0] = x;
    }
    __syncthreads();
    float r = red[0];
    __syncthreads();
    return r;
}

__global__ __launch_bounds__(1024) void gate_pred_kernel(float* __restrict__ out) {
    __shared__ float red[32];
    const int h = blockIdx.x, t = threadIdx.x;
    const int qn = t >> 5, kn = t & 31;
    float logit = -INFINITY;
    if (kn <= qn) {
        const float* a = g_gq + (h * NB_BLK + qn) * GATE_DIM;
        const float* b = g_gk + (h * NB_BLK + kn) * GATE_DIM;
        float acc = 0.f;
#pragma unroll
        for (int g = 0; g < GATE_DIM; g++) acc += a[g] * b[g];
        logit = acc * 0.125f;
    }
    float M = block_reduce_max(logit, red, t);
    float e = (logit == -INFINITY) ? 0.f : expf(logit - M);
    float L = block_reduce_sum(e, red, t);
    out[h * 1024 + t] = e / L;
}

__global__ __launch_bounds__(1024) void gate_target_kernel(float* __restrict__ out) {
    __shared__ float red[32];
    const int h = blockIdx.x, t = threadIdx.x;
    const int qn = t >> 5, kn = t & 31;
    float logit = -INFINITY;
    if (kn <= qn) {
        float b = g_bmax[h * 1024 + t];
        b = fminf(fmaxf(b, -50.f), 50.f);
        logit = b * 0.5f;
    }
    float M = block_reduce_max(logit, red, t);
    float e = (logit == -INFINITY) ? 0.f : expf(logit - M);
    float L = block_reduce_sum(e, red, t);
    out[h * 1024 + t] = e / L;
}

// -------------------- launch --------------------
extern "C" void kernel_launch(void* const* d_in, const int* in_sizes, int n_in,
                              void* d_out, int out_size) {
    const float* hs = (const float*)d_in[0];
    const float* cosp = (const float*)d_in[1];
    const float* sinp = (const float*)d_in[2];
    const float* W[4] = {(const float*)d_in[3], (const float*)d_in[4],
                         (const float*)d_in[5], (const float*)d_in[6]};
    const float* Wgq = (const float*)d_in[7];
    const float* Wgk = (const float*)d_in[8];
    float* out = (float*)d_out;

    void *pQ, *pK, *pV, *pC, *pAh, *pAl, *pWh, *pWl;
    cudaGetSymbolAddress(&pQ, g_Q);
    cudaGetSymbolAddress(&pK, g_K);
    cudaGetSymbolAddress(&pV, g_V);
    cudaGetSymbolAddress(&pC, g_C);
    cudaGetSymbolAddress(&pAh, g_Ah);
    cudaGetSymbolAddress(&pAl, g_Al);
    cudaGetSymbolAddress(&pWh, g_Wh);
    cudaGetSymbolAddress(&pWl, g_Wl);

    __nv_bfloat16* Ah = (__nv_bfloat16*)pAh;
    __nv_bfloat16* Al = (__nv_bfloat16*)pAl;
    float* outs[3] = {(float*)pQ, (float*)pK, (float*)pV};

    const int FLASH_SMEM = (64 * 128 + 64 * 65) * 4;
    cudaFuncSetAttribute(flash_kernel, cudaFuncAttributeMaxDynamicSharedMemorySize, FLASH_SMEM);
    cudaFuncSetAttribute(gemm_tc, cudaFuncAttributeMaxDynamicSharedMemorySize, GEMM_SMEM);

    const int N4W = E_DIM * E_DIM / 4;
    const int N4A = S_LEN * E_DIM / 4;

    // split activations + weights
    split_kernel<<<(N4A + 255) / 256, 256>>>(hs, Ah, Al, N4A);
    for (int i = 0; i < 4; i++) {
        split_kernel<<<(N4W + 255) / 256, 256>>>(
            W[i], (__nv_bfloat16*)pWh + (size_t)i * E_DIM * E_DIM,
            (__nv_bfloat16*)pWl + (size_t)i * E_DIM * E_DIM, N4W);
    }

    dim3 gg(E_DIM / BN, S_LEN / BM);  // 32 x 16
    for (int i = 0; i < 3; i++) {
        gemm_tc<<<gg, 512, GEMM_SMEM>>>(Ah, Al,
            (__nv_bfloat16*)pWh + (size_t)i * E_DIM * E_DIM,
            (__nv_bfloat16*)pWl + (size_t)i * E_DIM * E_DIM,
            outs[i], E_DIM, E_DIM);
    }

    rope_kernel<<<(2 * S_LEN * H_NUM * 64 + 255) / 256, 256>>>(cosp, sinp);

    flash_kernel<<<dim3(NB_BLK, H_NUM), 128, FLASH_SMEM>>>();

    block_mean_kernel<<<dim3(NB_BLK, H_NUM), 128>>>();
    gate_proj_kernel<<<dim3(NB_BLK, H_NUM), 128>>>(Wgq, Wgk);
    gate_pred_kernel<<<H_NUM, 1024>>>(out + (size_t)S_LEN * E_DIM);
    gate_target_kernel<<<H_NUM, 1024>>>(out + (size_t)S_LEN * E_DIM + H_NUM * NB_BLK * NB_BLK);

    // split attention context, final projection straight into d_out
    split_kernel<<<(N4A + 255) / 256, 256>>>((const float*)pC, Ah, Al, N4A);
    gemm_tc<<<gg, 512, GEMM_SMEM>>>(Ah, Al,
        (__nv_bfloat16*)pWh + (size_t)3 * E_DIM * E_DIM,
        (__nv_bfloat16*)pWl + (size_t)3 * E_DIM * E_DIM,
        out, E_DIM, E_DIM);
}

// round 7
// speedup vs baseline: 3.2626x; 1.6513x over previous
#include <cuda_runtime.h>
#include <cuda_bf16.h>
#include <math.h>
#include <cstdint>

// Problem constants
#define S_LEN 2048
#define E_DIM 4096
#define H_NUM 32
#define D_DIM 128
#define BS_BLK 64
#define NB_BLK 32
#define GATE_DIM 64

// GEMM tiling
#define BM 128
#define BN 128
#define BK 32

extern __shared__ char dynsmem[];

// -------------------- device scratch --------------------
__device__ float g_Q[S_LEN * E_DIM];
__device__ float g_K[S_LEN * E_DIM];
__device__ float g_V[S_LEN * E_DIM];
__device__ float g_C[S_LEN * E_DIM];
__device__ float g_bmax[H_NUM * NB_BLK * NB_BLK];
__device__ float g_qb[H_NUM * NB_BLK * D_DIM];
__device__ float g_kb[H_NUM * NB_BLK * D_DIM];
__device__ float g_gq[H_NUM * NB_BLK * GATE_DIM];
__device__ float g_gk[H_NUM * NB_BLK * GATE_DIM];
__device__ __nv_bfloat16 g_Ah[S_LEN * E_DIM];
__device__ __nv_bfloat16 g_Al[S_LEN * E_DIM];
__device__ __nv_bfloat16 g_Wh[4][E_DIM * E_DIM];
__device__ __nv_bfloat16 g_Wl[4][E_DIM * E_DIM];
// flash split buffers
__device__ __nv_bfloat16 g_Qh[S_LEN * E_DIM];
__device__ __nv_bfloat16 g_Ql[S_LEN * E_DIM];
__device__ __nv_bfloat16 g_Kh[S_LEN * E_DIM];
__device__ __nv_bfloat16 g_Kl[S_LEN * E_DIM];
__device__ __nv_bfloat16 g_Vh[S_LEN * E_DIM];
__device__ __nv_bfloat16 g_Vl[S_LEN * E_DIM];

// -------------------- helpers --------------------
__device__ __forceinline__ uint32_t smem_u32(const void* p) {
    uint32_t a;
    asm("{ .reg .u64 t; cvta.to.shared.u64 t, %1; cvt.u32.u64 %0, t; }" : "=r"(a) : "l"(p));
    return a;
}
__device__ __forceinline__ void cp16(uint32_t dst, const void* src) {
    asm volatile("cp.async.cg.shared.global [%0], [%1], 16;" :: "r"(dst), "l"(src));
}
__device__ __forceinline__ void ldsm4(uint32_t* r, uint32_t addr) {
    asm volatile("ldmatrix.sync.aligned.m8n8.x4.shared.b16 {%0,%1,%2,%3}, [%4];"
                 : "=r"(r[0]), "=r"(r[1]), "=r"(r[2]), "=r"(r[3]) : "r"(addr));
}
__device__ __forceinline__ void ldsm4t(uint32_t* r, uint32_t addr) {
    asm volatile("ldmatrix.sync.aligned.m8n8.x4.trans.shared.b16 {%0,%1,%2,%3}, [%4];"
                 : "=r"(r[0]), "=r"(r[1]), "=r"(r[2]), "=r"(r[3]) : "r"(addr));
}
__device__ __forceinline__ void mma16816(float* d, const uint32_t* a, const uint32_t* b) {
    asm volatile(
        "mma.sync.aligned.m16n8k16.row.col.f32.bf16.bf16.f32 "
        "{%0,%1,%2,%3}, {%4,%5,%6,%7}, {%8,%9}, {%0,%1,%2,%3};"
        : "+f"(d[0]), "+f"(d[1]), "+f"(d[2]), "+f"(d[3])
        : "r"(a[0]), "r"(a[1]), "r"(a[2]), "r"(a[3]), "r"(b[0]), "r"(b[1]));
}
__device__ __forceinline__ void split_pack(float p0, float p1, uint32_t& hi, uint32_t& lo) {
    __nv_bfloat16 h0 = __float2bfloat16(p0), h1 = __float2bfloat16(p1);
    float l0f = p0 - __bfloat162float(h0), l1f = p1 - __bfloat162float(h1);
    __nv_bfloat16 l0 = __float2bfloat16(l0f), l1 = __float2bfloat16(l1f);
    hi = ((uint32_t)__bfloat16_as_ushort(h1) << 16) | __bfloat16_as_ushort(h0);
    lo = ((uint32_t)__bfloat16_as_ushort(l1) << 16) | __bfloat16_as_ushort(l0);
}

// GEMM tile swizzle (128x32 bf16, rows of 64B)
__device__ __forceinline__ uint32_t sw_off(int r, int c4) {
    return (uint32_t)(((r >> 1) << 7) + (((((r & 1) << 2) + c4) ^ ((r >> 1) & 7)) << 4));
}
// flash tile swizzle (rows of 256B = 16 chunks of 16B)
__device__ __forceinline__ uint32_t fa_off(int r, int c16) {
    return (uint32_t)(r * 256 + ((c16 ^ (r & 7)) << 4));
}

// -------------------- split fp32 -> (hi, lo) bf16 --------------------
__global__ __launch_bounds__(256) void split_kernel(const float* __restrict__ src,
                                                    __nv_bfloat16* __restrict__ hi,
                                                    __nv_bfloat16* __restrict__ lo, int n4) {
    int i = blockIdx.x * blockDim.x + threadIdx.x;
    if (i >= n4) return;
    float4 x = ((const float4*)src)[i];
    float xs[4] = {x.x, x.y, x.z, x.w};
    uint32_t hp[2], lp[2];
#pragma unroll
    for (int j = 0; j < 2; j++) {
        __nv_bfloat16 h0 = __float2bfloat16(xs[2 * j]);
        __nv_bfloat16 h1 = __float2bfloat16(xs[2 * j + 1]);
        __nv_bfloat16 l0 = __float2bfloat16(xs[2 * j] - __bfloat162float(h0));
        __nv_bfloat16 l1 = __float2bfloat16(xs[2 * j + 1] - __bfloat162float(h1));
        hp[j] = ((uint32_t)__bfloat16_as_ushort(h1) << 16) | __bfloat16_as_ushort(h0);
        lp[j] = ((uint32_t)__bfloat16_as_ushort(l1) << 16) | __bfloat16_as_ushort(l0);
    }
    ((uint2*)hi)[i] = make_uint2(hp[0], hp[1]);
    ((uint2*)lo)[i] = make_uint2(lp[0], lp[1]);
}

// -------------------- mma.sync split-bf16 GEMM --------------------
#define GSTG 32768
#define GEMM_SMEM (2 * GSTG)

__device__ __forceinline__ void load_tile_mma(uint32_t dstbase, const __nv_bfloat16* src,
                                              int row0, int K, int k0, int tid) {
    int r = tid >> 2, c4 = tid & 3;
    cp16(dstbase + sw_off(r, c4), src + (size_t)(row0 + r) * K + k0 + c4 * 8);
}

__global__ __launch_bounds__(512, 1) void gemm_tc(const __nv_bfloat16* __restrict__ Ah,
                                                  const __nv_bfloat16* __restrict__ Al,
                                                  const __nv_bfloat16* __restrict__ Bh,
                                                  const __nv_bfloat16* __restrict__ Bl,
                                                  float* __restrict__ C, int K, int Ncols) {
    uint32_t sb = smem_u32(dynsmem);
    const int tid = threadIdx.x;
    const int wid = tid >> 5, lane = tid & 31;
    const int warp_m = wid >> 2, warp_n = wid & 3;
    const int base_m = warp_m * 32, base_n = warp_n * 32;
    const int bm = blockIdx.y * BM, bn = blockIdx.x * BN;

    float acc[2][4][4];
#pragma unroll
    for (int i = 0; i < 2; i++)
#pragma unroll
        for (int j = 0; j < 4; j++)
#pragma unroll
            for (int q = 0; q < 4; q++) acc[i][j][q] = 0.f;

    const int NKI = K / BK;

    load_tile_mma(sb + 0,     Ah, bm, K, 0, tid);
    load_tile_mma(sb + 8192,  Al, bm, K, 0, tid);
    load_tile_mma(sb + 16384, Bh, bn, K, 0, tid);
    load_tile_mma(sb + 24576, Bl, bn, K, 0, tid);
    asm volatile("cp.async.commit_group;");

    const int a_r = base_m + (lane & 15);
    const int a_cs = lane >> 4;
    const int b_n = base_n + (lane & 7) + ((lane >> 4) & 1) * 8;
    const int b_cs = (lane >> 3) & 1;

    for (int it = 0; it < NKI; ++it) {
        int cur = it & 1;
        if (it + 1 < NKI) {
            uint32_t sn = sb + (cur ^ 1) * GSTG;
            int k0 = (it + 1) * BK;
            load_tile_mma(sn + 0,     Ah, bm, K, k0, tid);
            load_tile_mma(sn + 8192,  Al, bm, K, k0, tid);
            load_tile_mma(sn + 16384, Bh, bn, K, k0, tid);
            load_tile_mma(sn + 24576, Bl, bn, K, k0, tid);
            asm volatile("cp.async.commit_group;");
            asm volatile("cp.async.wait_group 1;");
        } else {
            asm volatile("cp.async.wait_group 0;");
        }
        __syncthreads();

        uint32_t sA_h = sb + cur * GSTG;
        uint32_t sA_l = sA_h + 8192;
        uint32_t sB_h = sA_h + 16384;
        uint32_t sB_l = sA_h + 24576;

#pragma unroll
        for (int ks = 0; ks < 2; ++ks) {
            uint32_t ah[2][4], al[2][4], bh[2][4], bl[2][4];
#pragma unroll
            for (int tm = 0; tm < 2; tm++) {
                uint32_t off = sw_off(a_r + tm * 16, ks * 2 + a_cs);
                ldsm4(ah[tm], sA_h + off);
                ldsm4(al[tm], sA_l + off);
            }
#pragma unroll
            for (int tj = 0; tj < 2; tj++) {
                uint32_t off = sw_off(b_n + tj * 16, ks * 2 + b_cs);
                ldsm4(bh[tj], sB_h + off);
                ldsm4(bl[tj], sB_l + off);
            }
#pragma unroll
            for (int tm = 0; tm < 2; tm++)
#pragma unroll
                for (int tn = 0; tn < 4; tn++) {
                    const uint32_t* pbh = &bh[tn >> 1][(tn & 1) * 2];
                    const uint32_t* pbl = &bl[tn >> 1][(tn & 1) * 2];
                    mma16816(acc[tm][tn], ah[tm], pbh);
                    mma16816(acc[tm][tn], ah[tm], pbl);
                    mma16816(acc[tm][tn], al[tm], pbh);
                }
        }
        __syncthreads();
    }

#pragma unroll
    for (int tm = 0; tm < 2; tm++)
#pragma unroll
        for (int tn = 0; tn < 4; tn++) {
            int row = bm + base_m + tm * 16 + (lane >> 2);
            int col = bn + base_n + tn * 8 + 2 * (lane & 3);
            float* p0 = C + (size_t)row * Ncols + col;
            float* p1 = C + (size_t)(row + 8) * Ncols + col;
            p0[0] = acc[tm][tn][0];
            p0[1] = acc[tm][tn][1];
            p1[0] = acc[tm][tn][2];
            p1[1] = acc[tm][tn][3];
        }
}

// -------------------- RoPE --------------------
__global__ __launch_bounds__(256) void rope_kernel(const float* __restrict__ cs,
                                                   const float* __restrict__ sn) {
    const int PAIRS = S_LEN * H_NUM * (D_DIM / 2);
    int idx = blockIdx.x * blockDim.x + threadIdx.x;
    if (idx >= 2 * PAIRS) return;
    float* X = (idx >= PAIRS) ? g_K : g_Q;
    int p = (idx >= PAIRS) ? idx - PAIRS : idx;
    int s = p / (H_NUM * 64);
    int r = p % (H_NUM * 64);
    int h = r / 64;
    int d = r % 64;
    size_t base = (size_t)s * E_DIM + h * D_DIM + d;
    float x1 = X[base];
    float x2 = X[base + 64];
    float c1 = cs[s * D_DIM + d], s1 = sn[s * D_DIM + d];
    float c2 = cs[s * D_DIM + d + 64], s2 = sn[s * D_DIM + d + 64];
    X[base] = x1 * c1 - x2 * s1;
    X[base + 64] = x2 * c2 + x1 * s2;
}

// -------------------- Flash attention (mma.sync, split-bf16) --------------------
// CTA: 2 q-tiles (128 rows) x 1 head. 256 threads, 8 warps (wq = qtile in pair, wm = m16 idx).
// smem: Qh(32K) Ql(32K) + 2 stages of [Kh,Kl,Vh,Vl] 16K each = 192KB.
#define FA_SMEM (65536 + 2 * 65536)

__device__ __forceinline__ void fa_load_kv(uint32_t base, int h, int kt, int tid) {
    const __nv_bfloat16* srcs[4] = {g_Kh, g_Kl, g_Vh, g_Vl};
#pragma unroll
    for (int t = 0; t < 4; t++) {
        const __nv_bfloat16* s = srcs[t] + (size_t)(kt * 64) * E_DIM + h * D_DIM;
#pragma unroll
        for (int i = 0; i < 4; i++) {
            int id = tid + i * 256;
            int r = id >> 4, c16 = id & 15;
            cp16(base + t * 16384 + fa_off(r, c16), s + (size_t)r * E_DIM + c16 * 8);
        }
    }
}

__global__ __launch_bounds__(256, 1) void flash_mma_kernel() {
    __shared__ float bms[8];
    uint32_t sb = smem_u32(dynsmem);
    const int pair = blockIdx.x, h = blockIdx.y;
    const int tid = threadIdx.x, lane = tid & 31, wid = tid >> 5;
    const int wq = wid >> 2, wm = wid & 3;
    const int qt_own = pair * 2 + wq;
    const int qt1 = pair * 2 + 1;
    const int g = lane >> 2, c = lane & 3;
    const float scale = 0.08838834764831845f;

    const uint32_t QH = sb, QL = sb + 32768;
    const uint32_t ST0 = sb + 65536;

    // prologue: Q tiles + stage 0
    {
        const int qrow0 = pair * 128;
#pragma unroll
        for (int i = 0; i < 8; i++) {
            int id = tid + i * 256;
            int r = id >> 4, c16 = id & 15;
            uint32_t off = fa_off(r, c16);
            size_t gi = (size_t)(qrow0 + r) * E_DIM + h * D_DIM + c16 * 8;
            cp16(QH + off, g_Qh + gi);
            cp16(QL + off, g_Ql + gi);
        }
    }
    fa_load_kv(ST0, h, 0, tid);
    asm volatile("cp.async.commit_group;");

    float O[16][4];
#pragma unroll
    for (int i = 0; i < 16; i++)
#pragma unroll
        for (int e = 0; e < 4; e++) O[i][e] = 0.f;
    float mrow0 = -INFINITY, mrow1 = -INFINITY;
    float lrow0 = 0.f, lrow1 = 0.f;

    const int a_r = wq * 64 + wm * 16 + (lane & 15);
    const int a_cs = lane >> 4;
    const int b_r7 = (lane & 7) + ((lane >> 4) & 1) * 8;   // K (non-trans)
    const int b_cs = (lane >> 3) & 1;
    const int v_r7 = (lane & 7) + ((lane >> 3) & 1) * 8;   // V (trans)
    const int v_cs = lane >> 4;

    for (int kt = 0; kt <= qt1; ++kt) {
        uint32_t cur = ST0 + (uint32_t)(kt & 1) * 65536;
        if (kt + 1 <= qt1) {
            fa_load_kv(ST0 + (uint32_t)((kt + 1) & 1) * 65536, h, kt + 1, tid);
            asm volatile("cp.async.commit_group;");
            asm volatile("cp.async.wait_group 1;");
        } else {
            asm volatile("cp.async.wait_group 0;");
        }
        __syncthreads();

        const bool active = (kt <= qt_own);
        float S[8][4];
        uint32_t Ph[8][2], Pl[8][2];
        float bwm = -INFINITY;

        if (active) {
#pragma unroll
            for (int nt = 0; nt < 8; nt++)
#pragma unroll
                for (int e = 0; e < 4; e++) S[nt][e] = 0.f;

            // S = Q @ K^T  (3-term split)
#pragma unroll
            for (int ks = 0; ks < 8; ++ks) {
                uint32_t ah[4], al[4];
                uint32_t qoff = fa_off(a_r, 2 * ks + a_cs);
                ldsm4(ah, QH + qoff);
                ldsm4(al, QL + qoff);
#pragma unroll
                for (int nt2 = 0; nt2 < 4; nt2++) {
                    uint32_t kh[4], kl[4];
                    uint32_t koff = fa_off(nt2 * 16 + b_r7, 2 * ks + b_cs);
                    ldsm4(kh, cur + koff);
                    ldsm4(kl, cur + 16384 + koff);
#pragma unroll
                    for (int sub = 0; sub < 2; sub++) {
                        int nt = nt2 * 2 + sub;
                        mma16816(S[nt], ah, &kh[sub * 2]);
                        mma16816(S[nt], ah, &kl[sub * 2]);
                        mma16816(S[nt], al, &kh[sub * 2]);
                    }
                }
            }

            // scale + causal mask + maxes
            float nm0 = -INFINITY, nm1 = -INFINITY;
            const bool diag = (kt == qt_own);
            const int row0l = wm * 16 + g, row1l = row0l + 8;
#pragma unroll
            for (int nt = 0; nt < 8; nt++) {
#pragma unroll
                for (int e = 0; e < 4; e++) {
                    float v = S[nt][e] * scale;
                    if (diag) {
                        int col = nt * 8 + 2 * c + (e & 1);
                        int row = (e < 2) ? row0l : row1l;
                        if (col > row) v = -INFINITY;
                    }
                    S[nt][e] = v;
                    if (e < 2) nm0 = fmaxf(nm0, v); else nm1 = fmaxf(nm1, v);
                }
            }
            bwm = fmaxf(nm0, nm1);
#pragma unroll
            for (int o = 16; o; o >>= 1) bwm = fmaxf(bwm, __shfl_xor_sync(0xffffffffu, bwm, o));
            // row max across quad
            nm0 = fmaxf(nm0, __shfl_xor_sync(0xffffffffu, nm0, 1));
            nm0 = fmaxf(nm0, __shfl_xor_sync(0xffffffffu, nm0, 2));
            nm1 = fmaxf(nm1, __shfl_xor_sync(0xffffffffu, nm1, 1));
            nm1 = fmaxf(nm1, __shfl_xor_sync(0xffffffffu, nm1, 2));

            float mn0 = fmaxf(mrow0, nm0), mn1 = fmaxf(mrow1, nm1);
            float cor0 = __expf(mrow0 - mn0), cor1 = __expf(mrow1 - mn1);
            mrow0 = mn0; mrow1 = mn1;
            lrow0 *= cor0; lrow1 *= cor1;
#pragma unroll
            for (int nt = 0; nt < 16; nt++) {
                O[nt][0] *= cor0; O[nt][1] *= cor0;
                O[nt][2] *= cor1; O[nt][3] *= cor1;
            }
            // exp + split + pack
#pragma unroll
            for (int nt = 0; nt < 8; nt++) {
                float p0 = __expf(S[nt][0] - mn0), p1 = __expf(S[nt][1] - mn0);
                float p2 = __expf(S[nt][2] - mn1), p3 = __expf(S[nt][3] - mn1);
                lrow0 += p0 + p1;
                lrow1 += p2 + p3;
                split_pack(p0, p1, Ph[nt][0], Pl[nt][0]);
                split_pack(p2, p3, Ph[nt][1], Pl[nt][1]);
            }
        }

        if (active && lane == 0) bms[wid] = bwm;
        __syncthreads();
        if (active && wm == 0 && lane == 0) {
            float bm = fmaxf(fmaxf(bms[wq * 4 + 0], bms[wq * 4 + 1]),
                             fmaxf(bms[wq * 4 + 2], bms[wq * 4 + 3]));
            g_bmax[(h * NB_BLK + qt_own) * NB_BLK + kt] = bm;
        }

        if (active) {
            // O += P @ V (3-term split)
#pragma unroll
            for (int ks2 = 0; ks2 < 4; ks2++) {
                uint32_t pa_h[4] = {Ph[2 * ks2][0], Ph[2 * ks2][1],
                                    Ph[2 * ks2 + 1][0], Ph[2 * ks2 + 1][1]};
                uint32_t pa_l[4] = {Pl[2 * ks2][0], Pl[2 * ks2][1],
                                    Pl[2 * ks2 + 1][0], Pl[2 * ks2 + 1][1]};
#pragma unroll
                for (int nt2 = 0; nt2 < 8; nt2++) {
                    uint32_t vh[4], vl[4];
                    uint32_t voff = fa_off(ks2 * 16 + v_r7, nt2 * 2 + v_cs);
                    ldsm4t(vh, cur + 32768 + voff);
                    ldsm4t(vl, cur + 49152 + voff);
#pragma unroll
                    for (int sub = 0; sub < 2; sub++) {
                        int d = nt2 * 2 + sub;
                        mma16816(O[d], pa_h, &vh[sub * 2]);
                        mma16816(O[d], pa_h, &vl[sub * 2]);
                        mma16816(O[d], pa_l, &vh[sub * 2]);
                    }
                }
            }
        }
        __syncthreads();
    }

    // epilogue
    lrow0 += __shfl_xor_sync(0xffffffffu, lrow0, 1);
    lrow0 += __shfl_xor_sync(0xffffffffu, lrow0, 2);
    lrow1 += __shfl_xor_sync(0xffffffffu, lrow1, 1);
    lrow1 += __shfl_xor_sync(0xffffffffu, lrow1, 2);
    float inv0 = 1.f / lrow0, inv1 = 1.f / lrow1;
    int row0 = pair * 128 + wq * 64 + wm * 16 + g;
#pragma unroll
    for (int nt = 0; nt < 16; nt++) {
        int col = h * D_DIM + nt * 8 + 2 * c;
        float* p0 = g_C + (size_t)row0 * E_DIM + col;
        float* p1 = g_C + (size_t)(row0 + 8) * E_DIM + col;
        p0[0] = O[nt][0] * inv0;
        p0[1] = O[nt][1] * inv0;
        p1[0] = O[nt][2] * inv1;
        p1[1] = O[nt][3] * inv1;
    }
}

// -------------------- block means --------------------
__global__ __launch_bounds__(128) void block_mean_kernel() {
    const int nb = blockIdx.x, h = blockIdx.y, d = threadIdx.x;
    float sq = 0.f, sk = 0.f;
    for (int r = 0; r < 64; r++) {
        size_t idx = (size_t)(nb * 64 + r) * E_DIM + h * D_DIM + d;
        sq += g_Q[idx];
        sk += g_K[idx];
    }
    g_qb[(h * NB_BLK + nb) * D_DIM + d] = sq * (1.f / 64.f);
    g_kb[(h * NB_BLK + nb) * D_DIM + d] = sk * (1.f / 64.f);
}

// -------------------- gate projections --------------------
__global__ __launch_bounds__(128) void gate_proj_kernel(const float* __restrict__ Wgq,
                                                        const float* __restrict__ Wgk) {
    const int nb = blockIdx.x, h = blockIdx.y, t = threadIdx.x;
    const int g = t & 63;
    const bool isK = t >= 64;
    const float* src = isK ? g_kb : g_qb;
    const float* W = isK ? Wgk : Wgq;
    float a = 0.f;
    const float* sp = src + (h * NB_BLK + nb) * D_DIM;
    const float* wp = W + g * D_DIM;
#pragma unroll
    for (int d = 0; d < D_DIM; d++) a += sp[d] * wp[d];
    (isK ? g_gk : g_gq)[(h * NB_BLK + nb) * GATE_DIM + g] = a;
}

// -------------------- softmax helpers --------------------
__device__ __forceinline__ float block_reduce_max(float v, float* red, int t) {
#pragma unroll
    for (int o = 16; o; o >>= 1) v = fmaxf(v, __shfl_xor_sync(0xffffffffu, v, o));
    if ((t & 31) == 0) red[t >> 5] = v;
    __syncthreads();
    if (t < 32) {
        float x = red[t];
#pragma unroll
        for (int o = 16; o; o >>= 1) x = fmaxf(x, __shfl_xor_sync(0xffffffffu, x, o));
        if (t == 0) red[0] = x;
    }
    __syncthreads();
    float r = red[0];
    __syncthreads();
    return r;
}
__device__ __forceinline__ float block_reduce_sum(float v, float* red, int t) {
#pragma unroll
    for (int o = 16; o; o >>= 1) v += __shfl_xor_sync(0xffffffffu, v, o);
    if ((t & 31) == 0) red[t >> 5] = v;
    __syncthreads();
    if (t < 32) {
        float x = red[t];
#pragma unroll
        for (int o = 16; o; o >>= 1) x += __shfl_xor_sync(0xffffffffu, x, o);
        if (t == 0) red[0] = x;
    }
    __syncthreads();
    float r = red[0];
    __syncthreads();
    return r;
}

__global__ __launch_bounds__(1024) void gate_pred_kernel(float* __restrict__ out) {
    __shared__ float red[32];
    const int h = blockIdx.x, t = threadIdx.x;
    const int qn = t >> 5, kn = t & 31;
    float logit = -INFINITY;
    if (kn <= qn) {
        const float* a = g_gq + (h * NB_BLK + qn) * GATE_DIM;
        const float* b = g_gk + (h * NB_BLK + kn) * GATE_DIM;
        float acc = 0.f;
#pragma unroll
        for (int g = 0; g < GATE_DIM; g++) acc += a[g] * b[g];
        logit = acc * 0.125f;
    }
    float M = block_reduce_max(logit, red, t);
    float e = (logit == -INFINITY) ? 0.f : expf(logit - M);
    float L = block_reduce_sum(e, red, t);
    out[h * 1024 + t] = e / L;
}

__global__ __launch_bounds__(1024) void gate_target_kernel(float* __restrict__ out) {
    __shared__ float red[32];
    const int h = blockIdx.x, t = threadIdx.x;
    const int qn = t >> 5, kn = t & 31;
    float logit = -INFINITY;
    if (kn <= qn) {
        float b = g_bmax[h * 1024 + t];
        b = fminf(fmaxf(b, -50.f), 50.f);
        logit = b * 0.5f;
    }
    float M = block_reduce_max(logit, red, t);
    float e = (logit == -INFINITY) ? 0.f : expf(logit - M);
    float L = block_reduce_sum(e, red, t);
    out[h * 1024 + t] = e / L;
}

// -------------------- launch --------------------
extern "C" void kernel_launch(void* const* d_in, const int* in_sizes, int n_in,
                              void* d_out, int out_size) {
    const float* hs = (const float*)d_in[0];
    const float* cosp = (const float*)d_in[1];
    const float* sinp = (const float*)d_in[2];
    const float* W[4] = {(const float*)d_in[3], (const float*)d_in[4],
                         (const float*)d_in[5], (const float*)d_in[6]};
    const float* Wgq = (const float*)d_in[7];
    const float* Wgk = (const float*)d_in[8];
    float* out = (float*)d_out;

    void *pQ, *pK, *pV, *pC, *pAh, *pAl, *pWh, *pWl;
    void *pQh, *pQl, *pKh, *pKl, *pVh, *pVl;
    cudaGetSymbolAddress(&pQ, g_Q);
    cudaGetSymbolAddress(&pK, g_K);
    cudaGetSymbolAddress(&pV, g_V);
    cudaGetSymbolAddress(&pC, g_C);
    cudaGetSymbolAddress(&pAh, g_Ah);
    cudaGetSymbolAddress(&pAl, g_Al);
    cudaGetSymbolAddress(&pWh, g_Wh);
    cudaGetSymbolAddress(&pWl, g_Wl);
    cudaGetSymbolAddress(&pQh, g_Qh);
    cudaGetSymbolAddress(&pQl, g_Ql);
    cudaGetSymbolAddress(&pKh, g_Kh);
    cudaGetSymbolAddress(&pKl, g_Kl);
    cudaGetSymbolAddress(&pVh, g_Vh);
    cudaGetSymbolAddress(&pVl, g_Vl);

    __nv_bfloat16* Ah = (__nv_bfloat16*)pAh;
    __nv_bfloat16* Al = (__nv_bfloat16*)pAl;
    float* outs[3] = {(float*)pQ, (float*)pK, (float*)pV};

    cudaFuncSetAttribute(gemm_tc, cudaFuncAttributeMaxDynamicSharedMemorySize, GEMM_SMEM);
    cudaFuncSetAttribute(flash_mma_kernel, cudaFuncAttributeMaxDynamicSharedMemorySize, FA_SMEM);

    const int N4W = E_DIM * E_DIM / 4;
    const int N4A = S_LEN * E_DIM / 4;

    // split activations + weights
    split_kernel<<<(N4A + 255) / 256, 256>>>(hs, Ah, Al, N4A);
    for (int i = 0; i < 4; i++) {
        split_kernel<<<(N4W + 255) / 256, 256>>>(
            W[i], (__nv_bfloat16*)pWh + (size_t)i * E_DIM * E_DIM,
            (__nv_bfloat16*)pWl + (size_t)i * E_DIM * E_DIM, N4W);
    }

    dim3 gg(E_DIM / BN, S_LEN / BM);
    for (int i = 0; i < 3; i++) {
        gemm_tc<<<gg, 512, GEMM_SMEM>>>(Ah, Al,
            (__nv_bfloat16*)pWh + (size_t)i * E_DIM * E_DIM,
            (__nv_bfloat16*)pWl + (size_t)i * E_DIM * E_DIM,
            outs[i], E_DIM, E_DIM);
    }

    rope_kernel<<<(2 * S_LEN * H_NUM * 64 + 255) / 256, 256>>>(cosp, sinp);

    // split rotated Q,K and V for the mma flash path
    split_kernel<<<(N4A + 255) / 256, 256>>>((const float*)pQ, (__nv_bfloat16*)pQh,
                                             (__nv_bfloat16*)pQl, N4A);
    split_kernel<<<(N4A + 255) / 256, 256>>>((const float*)pK, (__nv_bfloat16*)pKh,
                                             (__nv_bfloat16*)pKl, N4A);
    split_kernel<<<(N4A + 255) / 256, 256>>>((const float*)pV, (__nv_bfloat16*)pVh,
                                             (__nv_bfloat16*)pVl, N4A);

    flash_mma_kernel<<<dim3(NB_BLK / 2, H_NUM), 256, FA_SMEM>>>();

    block_mean_kernel<<<dim3(NB_BLK, H_NUM), 128>>>();
    gate_proj_kernel<<<dim3(NB_BLK, H_NUM), 128>>>(Wgq, Wgk);
    gate_pred_kernel<<<H_NUM, 1024>>>(out + (size_t)S_LEN * E_DIM);
    gate_target_kernel<<<H_NUM, 1024>>>(out + (size_t)S_LEN * E_DIM + H_NUM * NB_BLK * NB_BLK);

    split_kernel<<<(N4A + 255) / 256, 256>>>((const float*)pC, Ah, Al, N4A);
    gemm_tc<<<gg, 512, GEMM_SMEM>>>(Ah, Al,
        (__nv_bfloat16*)pWh + (size_t)3 * E_DIM * E_DIM,
        (__nv_bfloat16*)pWl + (size_t)3 * E_DIM * E_DIM,
        out, E_DIM, E_DIM);
}